// round 15
// baseline (speedup 1.0000x reference)
#include <cuda_runtime.h>
#include <cuda_bf16.h>
#include <math.h>
#include <stdint.h>

#define MTOK  32768
#define HDIM  256
#define SLOTS 4096

typedef __nv_bfloat16 bf16;

// ======================= static scratch (no allocation) ========================
__device__ float g_xproj [MTOK*HDIM];
__device__ float g_query [MTOK*HDIM];
__device__ float g_kvo   [(size_t)MTOK*1024];   // [kv_lr(768) | opre(256)] per row
__device__ float g_bcat  [1024];
__device__ float g_gk    [SLOTS*HDIM];
__device__ float g_gv    [SLOTS*HDIM];
__device__ float g_gcnt  [SLOTS];

__device__ bf16 g_wsb[(size_t)MTOK*SLOTS];
__device__ bf16 g_xh [MTOK*HDIM], g_xl [MTOK*HDIM];
__device__ bf16 g_xph[MTOK*HDIM], g_xpl[MTOK*HDIM];
__device__ bf16 g_moh[MTOK*HDIM];
__device__ bf16 g_knh[MTOK*HDIM];
__device__ bf16 g_kmh[SLOTS*HDIM];
__device__ bf16 g_vth[HDIM*SLOTS];
__device__ bf16 g_winh[HDIM*HDIM], g_winl[HDIM*HDIM];
__device__ bf16 g_wqh [HDIM*HDIM], g_wql [HDIM*HDIM];
__device__ bf16 g_wch [1024*512],  g_wcl [1024*512];   // concat(W_kv^T, W_o^T)

// ======================= low-level helpers ======================================
__device__ __forceinline__ uint32_t smem_u32(const void* p) {
    uint32_t a;
    asm("{ .reg .u64 t; cvta.to.shared.u64 t, %1; cvt.u32.u64 %0, t; }" : "=r"(a) : "l"(p));
    return a;
}
__device__ __forceinline__ void cp16(uint32_t s, const void* g) {
    asm volatile("cp.async.cg.shared.global [%0], [%1], 16;" :: "r"(s), "l"(g));
}
#define CP_COMMIT() asm volatile("cp.async.commit_group;" ::: "memory")
#define CP_WAIT(n)  asm volatile("cp.async.wait_group %0;" :: "n"(n) : "memory")

#define LDM4(R, A) asm volatile( \
    "ldmatrix.sync.aligned.m8n8.x4.shared.b16 {%0,%1,%2,%3}, [%4];" \
    : "=r"((R)[0]), "=r"((R)[1]), "=r"((R)[2]), "=r"((R)[3]) : "r"(A))

__device__ __forceinline__ void mma16816(float* c, const uint32_t* a, const uint32_t* b) {
    asm volatile(
        "mma.sync.aligned.m16n8k16.row.col.f32.bf16.bf16.f32 "
        "{%0,%1,%2,%3}, {%4,%5,%6,%7}, {%8,%9}, {%0,%1,%2,%3};"
        : "+f"(c[0]), "+f"(c[1]), "+f"(c[2]), "+f"(c[3])
        : "r"(a[0]), "r"(a[1]), "r"(a[2]), "r"(a[3]), "r"(b[0]), "r"(b[1]));
}
__device__ __forceinline__ uint32_t packbf(float a, float b) {
    __nv_bfloat162 t;
    t.x = __float2bfloat16(a); t.y = __float2bfloat16(b);
    return *(uint32_t*)&t;
}

// ======================= fused conversions + zeroing =============================
#define CB1 8192u
#define CB2 9216u
#define CB3 10240u
#define CB4 10304u
#define CB5 10368u
#define CB6 10752u
#define CB7 10880u
#define CB8 10881u
#define CB9 12929u
#define CBT 12933u

__global__ __launch_bounds__(256)
void fused_conv(const float* __restrict__ x,   const float* __restrict__ Km,
                const float* __restrict__ Vm,  const float* __restrict__ W_in,
                const float* __restrict__ W_q, const float* __restrict__ W_kv,
                const float* __restrict__ W_o, const float* __restrict__ b_kv,
                const float* __restrict__ b_o)
{
    const uint32_t b = blockIdx.x;
    const int tid = threadIdx.x;
    if (b < CB1) {
        long i0 = (long)b * 1024 + tid;
#pragma unroll
        for (int k = 0; k < 4; k++) {
            long i = i0 + k * 256;
            float v = x[i];
            bf16 h = __float2bfloat16(v);
            g_xh[i] = h;
            g_xl[i] = __float2bfloat16(v - __bfloat162float(h));
        }
    } else if (b < CB2) {
        long i0 = (long)(b - CB1) * 1024 + tid;
#pragma unroll
        for (int k = 0; k < 4; k++) {
            long i = i0 + k * 256;
            g_kmh[i] = __float2bfloat16(Km[i]);
        }
    } else if (b < CB3) {
        long i0 = (long)(b - CB2) * 1024 + tid;
#pragma unroll
        for (int k = 0; k < 4; k++) {
            long i = i0 + k * 256;
            int r = (int)(i >> 8), c = (int)(i & 255);
            g_vth[(long)c * SLOTS + r] = __float2bfloat16(Vm[i]);
        }
    } else if (b < CB4) {
        long i0 = (long)(b - CB3) * 1024 + tid;
#pragma unroll
        for (int k = 0; k < 4; k++) {
            long i = i0 + k * 256;
            int r = (int)(i >> 8), c = (int)(i & 255);
            float v = W_in[i];
            bf16 h = __float2bfloat16(v);
            long o = (long)c * 256 + r;
            g_winh[o] = h;
            g_winl[o] = __float2bfloat16(v - __bfloat162float(h));
        }
    } else if (b < CB5) {
        long i0 = (long)(b - CB4) * 1024 + tid;
#pragma unroll
        for (int k = 0; k < 4; k++) {
            long i = i0 + k * 256;
            int r = (int)(i >> 8), c = (int)(i & 255);
            float v = W_q[i];
            bf16 h = __float2bfloat16(v);
            long o = (long)c * 256 + r;
            g_wqh[o] = h;
            g_wql[o] = __float2bfloat16(v - __bfloat162float(h));
        }
    } else if (b < CB6) {
        long i0 = (long)(b - CB5) * 1024 + tid;
#pragma unroll
        for (int k = 0; k < 4; k++) {
            long i = i0 + k * 256;
            int r = (int)(i / 768), c = (int)(i - (long)r * 768);
            float v = W_kv[i];
            bf16 h = __float2bfloat16(v);
            long o = (long)c * 512 + r;
            g_wch[o] = h;
            g_wcl[o] = __float2bfloat16(v - __bfloat162float(h));
        }
    } else if (b < CB7) {
        long i0 = (long)(b - CB6) * 1024 + tid;
#pragma unroll
        for (int k = 0; k < 4; k++) {
            long i = i0 + k * 256;
            int r = (int)(i >> 8), c = (int)(i & 255);
            float v = W_o[i];
            bf16 h = __float2bfloat16(v);
            long o = (long)(768 + c) * 512 + r;
            g_wch[o] = h;
            g_wcl[o] = __float2bfloat16(v - __bfloat162float(h));
        }
    } else if (b < CB8) {
#pragma unroll
        for (int k = 0; k < 4; k++) {
            int i = tid + k * 256;
            g_bcat[i] = (i < 768) ? b_kv[i] : b_o[i - 768];
        }
    } else if (b < CB9) {
        long i0 = (long)(b - CB8) * 1024 + tid;
#pragma unroll
        for (int k = 0; k < 4; k++) {
            long i = i0 + k * 256;
            if (i < (long)SLOTS * HDIM) g_gk[i] = 0.f;
            else g_gv[i - (long)SLOTS * HDIM] = 0.f;
        }
    } else {
        long i0 = (long)(b - CB9) * 1024 + tid;
#pragma unroll
        for (int k = 0; k < 4; k++) {
            long i = i0 + k * 256;
            if (i < SLOTS) g_gcnt[i] = 0.f;
        }
    }
}

// ======================= split-bf16 HMMA GEMM ====================================
#define STG   40960
#define GSMEM (3 * STG)
#define LDSB  80

template<int NS, bool LOA1>
__global__ __launch_bounds__(256, 1)
void gemm_bf16s(const bf16* __restrict__ Ah0, const bf16* __restrict__ Al0, int lda0,
                const bf16* __restrict__ Ah1, const bf16* __restrict__ Al1, int lda1,
                int K0, int K,
                const bf16* __restrict__ Bh, const bf16* __restrict__ Bl,
                const float* __restrict__ bias, float scale,
                float* __restrict__ C, int N,
                bf16* __restrict__ HiO, bf16* __restrict__ LoO,
                bf16* __restrict__ Cb)
{
    extern __shared__ __align__(128) char smx[];
    const uint32_t sb = smem_u32(smx);
    const int tid  = threadIdx.x;
    const int lane = tid & 31, wid = tid >> 5;
    const int wm   = wid & 3,  wn  = wid >> 2;
    const long blkm = (long)blockIdx.y * 128;
    const long blkn = (long)blockIdx.x * 128;
    const int NIT = K >> 5;

    const int r0 = tid >> 2,            c0 = (tid & 3);
    const int r1 = (tid + 256) >> 2,    c1 = ((tid + 256) & 3);

    float acc[2][8][4];
#pragma unroll
    for (int a = 0; a < 2; a++)
#pragma unroll
        for (int b = 0; b < 8; b++)
#pragma unroll
            for (int d = 0; d < 4; d++) acc[a][b][d] = 0.f;

#define LOAD_STAGE(IT) do {                                                        \
        const int _it = (IT);                                                      \
        const int _k0 = _it << 5;                                                  \
        const bf16 *_ah, *_al; long _lda; long _kc;                                \
        if (_k0 < K0) { _ah = Ah0; _al = Al0; _lda = lda0; _kc = _k0; }            \
        else          { _ah = Ah1; _al = Al1; _lda = lda1; _kc = _k0 - K0; }       \
        const bf16* _ar = _ah + blkm * _lda + _kc;                                 \
        const bf16* _br = Bh + blkn * (long)K + _k0;                               \
        const uint32_t _bs = sb + (uint32_t)(_it % 3) * STG;                       \
        cp16(_bs +         (uint32_t)(r0*LDSB + c0*16), _ar  + (long)r0*_lda + c0*8); \
        cp16(_bs +         (uint32_t)(r1*LDSB + c1*16), _ar  + (long)r1*_lda + c1*8); \
        if (NS == 3 && (LOA1 || _k0 < K0)) {                                       \
            const bf16* _alr = _al + blkm * _lda + _kc;                            \
            cp16(_bs + 10240 + (uint32_t)(r0*LDSB + c0*16), _alr + (long)r0*_lda + c0*8); \
            cp16(_bs + 10240 + (uint32_t)(r1*LDSB + c1*16), _alr + (long)r1*_lda + c1*8); \
        }                                                                          \
        cp16(_bs + 20480 + (uint32_t)(r0*LDSB + c0*16), _br  + (long)r0*K + c0*8);    \
        cp16(_bs + 20480 + (uint32_t)(r1*LDSB + c1*16), _br  + (long)r1*K + c1*8);    \
        if (NS >= 2) {                                                             \
            const bf16* _blr = Bl + blkn * (long)K + _k0;                          \
            cp16(_bs + 30720 + (uint32_t)(r0*LDSB + c0*16), _blr + (long)r0*K + c0*8);    \
            cp16(_bs + 30720 + (uint32_t)(r1*LDSB + c1*16), _blr + (long)r1*K + c1*8);    \
        }                                                                          \
        CP_COMMIT();                                                               \
    } while (0)

    LOAD_STAGE(0);
    if (NIT > 1) LOAD_STAGE(1);

    const uint32_t a_off = (uint32_t)((wm*32 + (lane & 15)) * LDSB + (lane >> 4) * 16);
    const uint32_t b_off = (uint32_t)((wn*64 + ((lane >> 4) << 3) + (lane & 7)) * LDSB
                                      + ((lane >> 3) & 1) * 16);

    for (int it = 0; it < NIT; it++) {
        if (it + 1 < NIT) CP_WAIT(1); else CP_WAIT(0);
        __syncthreads();
        const bool doAL = (NS == 3) && (LOA1 || (it << 5) < K0);
        const uint32_t base = sb + (uint32_t)(it % 3) * STG;
#pragma unroll
        for (int kk = 0; kk < 2; kk++) {
            const uint32_t ka = base + a_off + kk * 32;
            const uint32_t kb = base + b_off + kk * 32;
            uint32_t AH[2][4], AL[2][4], BH[4][4], BL[4][4];
            LDM4(AH[0], ka);
            LDM4(AH[1], ka + 16 * LDSB);
            if (NS == 3 && doAL) {
                LDM4(AL[0], ka + 10240);
                LDM4(AL[1], ka + 10240 + 16 * LDSB);
            }
#pragma unroll
            for (int p = 0; p < 4; p++) {
                LDM4(BH[p], kb + 20480 + p * 16 * LDSB);
                if (NS >= 2) LDM4(BL[p], kb + 30720 + p * 16 * LDSB);
            }
#pragma unroll
            for (int mf = 0; mf < 2; mf++)
#pragma unroll
                for (int nf = 0; nf < 8; nf++) {
                    const uint32_t* bh = &BH[nf >> 1][(nf & 1) * 2];
                    mma16816(acc[mf][nf], AH[mf], bh);
                    if (NS >= 2) {
                        const uint32_t* bl = &BL[nf >> 1][(nf & 1) * 2];
                        mma16816(acc[mf][nf], AH[mf], bl);
                    }
                    if (NS == 3 && doAL) mma16816(acc[mf][nf], AL[mf], bh);
                }
        }
        if (it + 2 < NIT) LOAD_STAGE(it + 2);
    }

#pragma unroll
    for (int mf = 0; mf < 2; mf++) {
        const long m0 = blkm + wm * 32 + mf * 16 + (lane >> 2);
#pragma unroll
        for (int nf = 0; nf < 8; nf++) {
            const long n0 = blkn + wn * 64 + nf * 8 + (lane & 3) * 2;
            float b0 = bias ? bias[n0]     : 0.f;
            float b1 = bias ? bias[n0 + 1] : 0.f;
            float2 v0, v1;
            v0.x = acc[mf][nf][0] * scale + b0;
            v0.y = acc[mf][nf][1] * scale + b1;
            v1.x = acc[mf][nf][2] * scale + b0;
            v1.y = acc[mf][nf][3] * scale + b1;
            if (Cb) {
                *(uint32_t*)(Cb + m0 * (long)N + n0)       = packbf(v0.x, v0.y);
                *(uint32_t*)(Cb + (m0 + 8) * (long)N + n0) = packbf(v1.x, v1.y);
            } else {
                *(float2*)(C + m0 * (long)N + n0)       = v0;
                *(float2*)(C + (m0 + 8) * (long)N + n0) = v1;
                if (HiO) {
                    __nv_bfloat162 h0, h1, l0, l1;
                    h0.x = __float2bfloat16(v0.x); h0.y = __float2bfloat16(v0.y);
                    h1.x = __float2bfloat16(v1.x); h1.y = __float2bfloat16(v1.y);
                    l0.x = __float2bfloat16(v0.x - __bfloat162float(h0.x));
                    l0.y = __float2bfloat16(v0.y - __bfloat162float(h0.y));
                    l1.x = __float2bfloat16(v1.x - __bfloat162float(h1.x));
                    l1.y = __float2bfloat16(v1.y - __bfloat162float(h1.y));
                    *(__nv_bfloat162*)(HiO + m0 * (long)N + n0)       = h0;
                    *(__nv_bfloat162*)(HiO + (m0 + 8) * (long)N + n0) = h1;
                    *(__nv_bfloat162*)(LoO + m0 * (long)N + n0)       = l0;
                    *(__nv_bfloat162*)(LoO + (m0 + 8) * (long)N + n0) = l1;
                }
            }
        }
    }
#undef LOAD_STAGE
}

// ======================= fused flash attention (occ-2) ===========================
// CTA: 128 threads (4 warps), 64 query rows (warp = 16 rows), 32-slot K/V tiles
// double-buffered. Two CTAs per SM hide softmax/sync latency under MMAs.
#define LDQ 528
#define LDK 528
#define LDV 80
#define OQ  0
#define OK0 33792
#define OK1 50688
#define OV0 67584
#define OV1 88064
#define FA_SMEM 108544

#define LOADK(S0, BUF) do {                                                 \
        const bf16* _kh = Kh + (long)(S0) * HDIM;                           \
        const uint32_t _b = sb + ((BUF) ? OK1 : OK0);                       \
        _Pragma("unroll")                                                   \
        for (int _i = 0; _i < 8; _i++) {                                    \
            int _idx = tid + (_i << 7);                                     \
            int _r = _idx >> 5, _c = _idx & 31;                             \
            cp16(_b + (uint32_t)(_r * LDK + _c * 16), _kh + (long)_r * HDIM + _c * 8); \
        }                                                                   \
        CP_COMMIT();                                                        \
    } while (0)

#define LOADV(S0, BUF) do {                                                 \
        const uint32_t _b = sb + ((BUF) ? OV1 : OV0);                       \
        _Pragma("unroll")                                                   \
        for (int _i = 0; _i < 8; _i++) {                                    \
            int _idx = tid + (_i << 7);                                     \
            int _r = _idx >> 2, _c = _idx & 3;                              \
            cp16(_b + (uint32_t)(_r * LDV + _c * 16), Vth + (long)_r * SLOTS + (S0) + _c * 8); \
        }                                                                   \
        CP_COMMIT();                                                        \
    } while (0)

__global__ __launch_bounds__(128, 2)
void attn_fused(const float* __restrict__ Qpre, const float* __restrict__ gq,
                const float* __restrict__ beq,
                const bf16* __restrict__ Kh, const bf16* __restrict__ Vth,
                bf16* __restrict__ MOh, float* __restrict__ surp)
{
    extern __shared__ __align__(128) char smx[];
    const uint32_t sb = smem_u32(smx);
    const int tid = threadIdx.x, lane = tid & 31, wid = tid >> 5;   // wid 0..3
    const long row0 = (long)blockIdx.x * 64;

    LOADK(0, 0);
    LOADV(0, 0);

    // --- fused LN + exact GELU prologue (overlaps K/V cp.async) ---
    {
        float gv[8], bv[8];
        *(float4*)&gv[0] = *(const float4*)(gq  + lane * 8);
        *(float4*)&gv[4] = *(const float4*)(gq  + lane * 8 + 4);
        *(float4*)&bv[0] = *(const float4*)(beq + lane * 8);
        *(float4*)&bv[4] = *(const float4*)(beq + lane * 8 + 4);
#pragma unroll 2
        for (int rr = 0; rr < 16; rr++) {
            const int rl = wid * 16 + rr;
            const float* qr = Qpre + (row0 + rl) * HDIM + lane * 8;
            float v[8];
            *(float4*)&v[0] = *(const float4*)qr;
            *(float4*)&v[4] = *(const float4*)(qr + 4);
            float s = 0.f;
#pragma unroll
            for (int j = 0; j < 8; j++) s += v[j];
#pragma unroll
            for (int o = 16; o > 0; o >>= 1) s += __shfl_xor_sync(0xffffffffu, s, o);
            const float mean = s * (1.f / 256.f);
            float sq = 0.f;
#pragma unroll
            for (int j = 0; j < 8; j++) { float d = v[j] - mean; sq += d * d; }
#pragma unroll
            for (int o = 16; o > 0; o >>= 1) sq += __shfl_xor_sync(0xffffffffu, sq, o);
            const float rstd = rsqrtf(sq * (1.f / 256.f) + 1e-5f);
            uint32_t pk[4];
#pragma unroll
            for (int j = 0; j < 4; j++) {
                float t0 = (v[2*j]   - mean) * rstd * gv[2*j]   + bv[2*j];
                float t1 = (v[2*j+1] - mean) * rstd * gv[2*j+1] + bv[2*j+1];
                float g0 = 0.5f * t0 * (1.f + erff(t0 * 0.70710678f));
                float g1 = 0.5f * t1 * (1.f + erff(t1 * 0.70710678f));
                pk[j] = packbf(g0, g1);
            }
            uint32_t dst = sb + OQ + (uint32_t)(rl * LDQ + lane * 16);
            asm volatile("st.shared.v4.b32 [%0], {%1,%2,%3,%4};"
                         :: "r"(dst), "r"(pk[0]), "r"(pk[1]), "r"(pk[2]), "r"(pk[3]));
        }
    }

    const uint32_t a_off  = sb + OQ + (uint32_t)((wid * 16 + (lane & 15)) * LDQ + (lane >> 4) * 16);
    const uint32_t bk_off = (uint32_t)(((((lane >> 4) << 3) + (lane & 7)) * LDK) + ((lane >> 3) & 1) * 16);
    const uint32_t bv_off = (uint32_t)(((((lane >> 4) << 3) + (lane & 7)) * LDV) + ((lane >> 3) & 1) * 16);

    float oacc[32][4];
#pragma unroll
    for (int i = 0; i < 32; i++)
#pragma unroll
        for (int j = 0; j < 4; j++) oacc[i][j] = 0.f;
    float m0 = -INFINITY, m1 = -INFINITY, l0 = 0.f, l1 = 0.f;

    for (int s = 0; s < 128; s++) {
        const uint32_t kb_base = sb + ((s & 1) ? OK1 : OK0);
        const uint32_t vb_base = sb + ((s & 1) ? OV1 : OV0);

        CP_WAIT(1);                 // K(s) resident
        __syncthreads();
        LOADK((s + 1 < 128 ? (s + 1) * 32 : 0), (s + 1) & 1);

        float sacc[4][4];
#pragma unroll
        for (int nf = 0; nf < 4; nf++)
#pragma unroll
            for (int j = 0; j < 4; j++) sacc[nf][j] = 0.f;

#pragma unroll 4
        for (int kk = 0; kk < 16; kk++) {
            uint32_t A[4], BH[2][4];
            LDM4(A, a_off + kk * 32);
#pragma unroll
            for (int p = 0; p < 2; p++)
                LDM4(BH[p], kb_base + bk_off + (uint32_t)(p * 16 * LDK) + kk * 32);
#pragma unroll
            for (int nf = 0; nf < 4; nf++)
                mma16816(sacc[nf], A, &BH[nf >> 1][(nf & 1) * 2]);
        }

        float tm0 = -INFINITY, tm1 = -INFINITY;
#pragma unroll
        for (int nf = 0; nf < 4; nf++) {
            tm0 = fmaxf(tm0, fmaxf(sacc[nf][0], sacc[nf][1]));
            tm1 = fmaxf(tm1, fmaxf(sacc[nf][2], sacc[nf][3]));
        }
        tm0 = fmaxf(tm0, __shfl_xor_sync(0xffffffffu, tm0, 1));
        tm0 = fmaxf(tm0, __shfl_xor_sync(0xffffffffu, tm0, 2));
        tm1 = fmaxf(tm1, __shfl_xor_sync(0xffffffffu, tm1, 1));
        tm1 = fmaxf(tm1, __shfl_xor_sync(0xffffffffu, tm1, 2));
        tm0 *= 0.0625f; tm1 *= 0.0625f;
        const float nm0 = fmaxf(m0, tm0), nm1 = fmaxf(m1, tm1);
        const float al0 = __expf(m0 - nm0),  al1 = __expf(m1 - nm1);

        uint32_t PH[2][4];
        float ls0 = 0.f, ls1 = 0.f;
#pragma unroll
        for (int nf = 0; nf < 4; nf++) {
            float p0 = __expf(fmaf(sacc[nf][0], 0.0625f, -nm0));
            float p1 = __expf(fmaf(sacc[nf][1], 0.0625f, -nm0));
            float p2 = __expf(fmaf(sacc[nf][2], 0.0625f, -nm1));
            float p3 = __expf(fmaf(sacc[nf][3], 0.0625f, -nm1));
            ls0 += p0 + p1; ls1 += p2 + p3;
            const int kc = nf >> 1, bi = (nf & 1) * 2;
            PH[kc][bi]     = packbf(p0, p1);
            PH[kc][bi + 1] = packbf(p2, p3);
        }
        ls0 += __shfl_xor_sync(0xffffffffu, ls0, 1);
        ls0 += __shfl_xor_sync(0xffffffffu, ls0, 2);
        ls1 += __shfl_xor_sync(0xffffffffu, ls1, 1);
        ls1 += __shfl_xor_sync(0xffffffffu, ls1, 2);
        l0 = l0 * al0 + ls0;
        l1 = l1 * al1 + ls1;
        m0 = nm0; m1 = nm1;
#pragma unroll
        for (int i = 0; i < 32; i++) {
            oacc[i][0] *= al0; oacc[i][1] *= al0;
            oacc[i][2] *= al1; oacc[i][3] *= al1;
        }

        CP_WAIT(1);                 // V(s) resident
        __syncthreads();
        LOADV((s + 1 < 128 ? (s + 1) * 32 : 0), (s + 1) & 1);

#pragma unroll
        for (int kc = 0; kc < 2; kc++) {
#pragma unroll
            for (int g = 0; g < 16; g++) {
                uint32_t VH[4];
                LDM4(VH, vb_base + bv_off + (uint32_t)(g * 16 * LDV) + kc * 32);
                mma16816(oacc[2*g],     PH[kc], &VH[0]);
                mma16816(oacc[2*g + 1], PH[kc], &VH[2]);
            }
        }
    }
    CP_WAIT(0);

    const float inv0 = 1.f / l0, inv1 = 1.f / l1;
    const long gr0 = row0 + wid * 16 + (lane >> 2);
    const long gr1 = gr0 + 8;
#pragma unroll
    for (int nf2 = 0; nf2 < 32; nf2++) {
        const int c = nf2 * 8 + (lane & 3) * 2;
        *(uint32_t*)(MOh + gr0 * HDIM + c) = packbf(oacc[nf2][0] * inv0, oacc[nf2][1] * inv0);
        *(uint32_t*)(MOh + gr1 * HDIM + c) = packbf(oacc[nf2][2] * inv1, oacc[nf2][3] * inv1);
    }
    if ((lane & 3) == 0) {
        surp[gr0] = 1.f - inv0;
        surp[gr1] = 1.f - inv1;
    }
}

// ======================= reductions ==============================================
__device__ __forceinline__ float block_sum_256(float v, float* red)
{
#pragma unroll
    for (int o = 16; o > 0; o >>= 1) v += __shfl_xor_sync(0xffffffffu, v, o);
    if ((threadIdx.x & 31) == 0) red[threadIdx.x >> 5] = v;
    __syncthreads();
    float t = 0.f;
#pragma unroll
    for (int i = 0; i < 8; i++) t += red[i];
    __syncthreads();
    return t;
}
__device__ __forceinline__ float block_max_256(float v, float* red)
{
#pragma unroll
    for (int o = 16; o > 0; o >>= 1) v = fmaxf(v, __shfl_xor_sync(0xffffffffu, v, o));
    if ((threadIdx.x & 31) == 0) red[threadIdx.x >> 5] = v;
    __syncthreads();
    float t = -INFINITY;
#pragma unroll
    for (int i = 0; i < 8; i++) t = fmaxf(t, red[i]);
    __syncthreads();
    return t;
}

// ======================= merged kv LN+GELU + final double-LN =====================
__global__ __launch_bounds__(256)
void ln_kv_final(float* __restrict__ kvo, const float* __restrict__ gkv,
                 const float* __restrict__ bekv, bf16* __restrict__ knh,
                 float* __restrict__ lr,
                 const float* __restrict__ xproj,
                 const float* __restrict__ go, const float* __restrict__ beo,
                 const float* __restrict__ g1, const float* __restrict__ be1,
                 float* __restrict__ out)
{
    __shared__ float red[8];
    const long row = blockIdx.x; const int tid = threadIdx.x;
    float* xr = kvo + row * 1024;

    float vals[3];
    float s = 0.f;
#pragma unroll
    for (int i = 0; i < 3; i++) { vals[i] = xr[tid + (i << 8)]; s += vals[i]; }
    float mean = block_sum_256(s, red) * (1.f / 768.f);
    float sq = 0.f;
#pragma unroll
    for (int i = 0; i < 3; i++) { float d = vals[i] - mean; sq += d * d; }
    float var  = block_sum_256(sq, red) * (1.f / 768.f);
    float rstd = rsqrtf(var + 1e-5f);
    float gout[3];
#pragma unroll
    for (int i = 0; i < 3; i++) {
        int c = tid + (i << 8);
        float t = (vals[i] - mean) * rstd * gkv[c] + bekv[c];
        gout[i] = 0.5f * t * (1.f + erff(t * 0.70710678f));
    }
    xr[tid]       = gout[0];
    xr[tid + 256] = gout[1];
    knh[row * HDIM + tid] = __float2bfloat16(gout[0]);
    float sg = 1.f / (1.f + __expf(-gout[2]));
    float tot = block_sum_256(sg, red);
    if (tid == 0) lr[row] = tot * (1.f / 256.f);

    float v    = xr[768 + tid];
    float m1   = block_sum_256(v, red) * (1.f / 256.f);
    float d    = v - m1;
    float var2 = block_sum_256(d * d, red) * (1.f / 256.f);
    float t    = d * rsqrtf(var2 + 1e-5f) * go[tid] + beo[tid];
    float u    = t + xproj[row * HDIM + tid];
    float m2   = block_sum_256(u, red) * (1.f / 256.f);
    float d2   = u - m2;
    float v2   = block_sum_256(d2 * d2, red) * (1.f / 256.f);
    out[row * HDIM + tid] = d2 * rsqrtf(v2 + 1e-5f) * g1[tid] + be1[tid];
}

__global__ void memupd_kernel(const float* __restrict__ Km, const float* __restrict__ Vm,
                              float* __restrict__ Kout, float* __restrict__ Vout)
{
    int i = blockIdx.x * blockDim.x + threadIdx.x;
    float cnt = g_gcnt[i >> 8];
    float k = Km[i], v = Vm[i];
    Kout[i] = k + 0.1f * (g_gk[i] - cnt * k);
    Vout[i] = v + 0.1f * (g_gv[i] - cnt * v);
}

// ======================= exact argmax + gated scatter ===========================
__global__ __launch_bounds__(256)
void argmax_scatter(const bf16* __restrict__ wsim, const float* __restrict__ kvo,
                    const float* __restrict__ Km, const float* __restrict__ surp)
{
    __shared__ float red[8];
    __shared__ int s_cnt;
    __shared__ int s_cand[128];
    const long row = blockIdx.x;
    const int tid = threadIdx.x;
    const bf16* wr = wsim + row * SLOTS;
    float v[16], mloc = -INFINITY;
#pragma unroll
    for (int i = 0; i < 16; i++) {
        v[i] = __bfloat162float(wr[tid + (i << 8)]);
        mloc = fmaxf(mloc, v[i]);
    }
    float m = block_max_256(mloc, red);
    if (tid == 0) s_cnt = 0;
    __syncthreads();
#pragma unroll
    for (int i = 0; i < 16; i++) {
        if (v[i] >= m - 1e-1f) {
            int p = atomicAdd(&s_cnt, 1);
            if (p < 128) s_cand[p] = tid + (i << 8);
        }
    }
    __syncthreads();
    int n = s_cnt < 128 ? s_cnt : 128;
    const float kn = kvo[row * 1024 + tid];
    float bestv = -INFINITY; int besti = 0x7fffffff;
    for (int j = 0; j < n; j++) {
        int slot = s_cand[j];
        float s = block_sum_256(kn * Km[(long)slot * HDIM + tid], red);
        if (s > bestv || (s == bestv && slot < besti)) { bestv = s; besti = slot; }
    }
    float gate = surp[row];
    atomicAdd(&g_gk[(long)besti * HDIM + tid], gate * kn);
    atomicAdd(&g_gv[(long)besti * HDIM + tid], gate * kvo[row * 1024 + 256 + tid]);
    if (tid == 0) atomicAdd(&g_gcnt[besti], gate);
}

// =================================================================================
extern "C" void kernel_launch(void* const* d_in, const int* in_sizes, int n_in,
                              void* d_out, int out_size)
{
    const float* x    = (const float*)d_in[0];
    const float* W_in = (const float*)d_in[1];
    const float* b_in = (const float*)d_in[2];
    const float* W_q  = (const float*)d_in[3];
    const float* b_q  = (const float*)d_in[4];
    const float* gq   = (const float*)d_in[5];
    const float* beq  = (const float*)d_in[6];
    const float* Km   = (const float*)d_in[7];
    const float* Vm   = (const float*)d_in[8];
    const float* W_kv = (const float*)d_in[9];
    const float* b_kv = (const float*)d_in[10];
    const float* gkv  = (const float*)d_in[11];
    const float* bekv = (const float*)d_in[12];
    const float* W_o  = (const float*)d_in[13];
    const float* b_o  = (const float*)d_in[14];
    const float* go   = (const float*)d_in[15];
    const float* beo  = (const float*)d_in[16];
    const float* g1   = (const float*)d_in[17];
    const float* be1  = (const float*)d_in[18];

    float* out    = (float*)d_out;
    float* o_out  = out;
    float* k_out  = out + 8388608;
    float* v_out  = out + 9437184;
    float* s_out  = out + 10485760;
    float* lr_out = out + 10518528;

    float *p_xproj, *p_query, *p_kvo, *p_bcat;
    cudaGetSymbolAddress((void**)&p_xproj, g_xproj);
    cudaGetSymbolAddress((void**)&p_query, g_query);
    cudaGetSymbolAddress((void**)&p_kvo,   g_kvo);
    cudaGetSymbolAddress((void**)&p_bcat,  g_bcat);
    bf16 *wsb,*xh,*xl,*xph,*xpl,*moh,*knh,*kmh,*vth;
    bf16 *winh,*winl,*wqh,*wql,*wch,*wcl;
    cudaGetSymbolAddress((void**)&wsb, g_wsb);
    cudaGetSymbolAddress((void**)&xh,  g_xh);  cudaGetSymbolAddress((void**)&xl,  g_xl);
    cudaGetSymbolAddress((void**)&xph, g_xph); cudaGetSymbolAddress((void**)&xpl, g_xpl);
    cudaGetSymbolAddress((void**)&moh, g_moh);
    cudaGetSymbolAddress((void**)&knh, g_knh);
    cudaGetSymbolAddress((void**)&kmh, g_kmh);
    cudaGetSymbolAddress((void**)&vth, g_vth);
    cudaGetSymbolAddress((void**)&winh,g_winh);cudaGetSymbolAddress((void**)&winl,g_winl);
    cudaGetSymbolAddress((void**)&wqh, g_wqh); cudaGetSymbolAddress((void**)&wql, g_wql);
    cudaGetSymbolAddress((void**)&wch, g_wch); cudaGetSymbolAddress((void**)&wcl, g_wcl);

    cudaFuncSetAttribute((const void*)gemm_bf16s<3,true>,  cudaFuncAttributeMaxDynamicSharedMemorySize, GSMEM);
    cudaFuncSetAttribute((const void*)gemm_bf16s<3,false>, cudaFuncAttributeMaxDynamicSharedMemorySize, GSMEM);
    cudaFuncSetAttribute((const void*)gemm_bf16s<2,true>,  cudaFuncAttributeMaxDynamicSharedMemorySize, GSMEM);
    cudaFuncSetAttribute((const void*)gemm_bf16s<1,true>,  cudaFuncAttributeMaxDynamicSharedMemorySize, GSMEM);
    cudaFuncSetAttribute((const void*)attn_fused,          cudaFuncAttributeMaxDynamicSharedMemorySize, FA_SMEM);

    fused_conv<<<CBT, 256>>>(x, Km, Vm, W_in, W_q, W_kv, W_o, b_kv, b_o);

    // x_proj = x @ W_in + b_in  (NS=3; fused hi/lo out)
    gemm_bf16s<3,true><<<dim3(2,256), 256, GSMEM>>>(xh, xl, 256, xh, xl, 256, 256, 256,
                                                    winh, winl, b_in, 1.f, p_xproj, 256, xph, xpl, nullptr);

    // q_pre = x_proj @ W_q + b_q  (NS=2); LN+GELU fused into attn prologue
    gemm_bf16s<2,true><<<dim3(2,256), 256, GSMEM>>>(xph, nullptr, 256, xph, nullptr, 256, 256, 256,
                                                    wqh, wql, b_q, 1.f, p_query, 256, nullptr, nullptr, nullptr);

    // fused: LN+GELU(q) -> sim (NS=1) -> softmax -> mem_out (PV NS=1) + surprise
    attn_fused<<<512, 128, FA_SMEM>>>(p_query, gq, beq, kmh, vth, moh, s_out);

    // merged [kv_lr | opre] GEMM (NS=3, mo half lo-free)
    gemm_bf16s<3,false><<<dim3(8,256), 256, GSMEM>>>(xph, xpl, 256, moh, nullptr, 256, 256, 512,
                                                     wch, wcl, p_bcat, 1.f, p_kvo, 1024, nullptr, nullptr, nullptr);

    // merged: LN+GELU(kv) + lr + final double-LN -> out
    ln_kv_final<<<32768, 256>>>(p_kvo, gkv, bekv, knh, lr_out,
                                p_xproj, go, beo, g1, be1, o_out);

    // wsim = key_new @ K_mem^T  (NS=1, bf16 out), then exact argmax + scatter
    gemm_bf16s<1,true><<<dim3(32,256), 256, GSMEM>>>(knh, nullptr, 256, knh, nullptr, 256, 256, 256,
                                                     kmh, nullptr, nullptr, 1.f, nullptr, SLOTS, nullptr, nullptr, wsb);
    argmax_scatter<<<32768, 256>>>(wsb, p_kvo, Km, s_out);
    memupd_kernel<<<4096, 256>>>(Km, Vm, k_out, v_out);
}

// round 16
// speedup vs baseline: 1.0604x; 1.0604x over previous
#include <cuda_runtime.h>
#include <cuda_bf16.h>
#include <math.h>
#include <stdint.h>

#define MTOK  32768
#define HDIM  256
#define SLOTS 4096

typedef __nv_bfloat16 bf16;

// ======================= static scratch (no allocation) ========================
__device__ float g_xproj [MTOK*HDIM];
__device__ float g_query [MTOK*HDIM];
__device__ float g_kvo   [(size_t)MTOK*1024];   // [kv_lr(768) | opre(256)] per row
__device__ float g_bcat  [1024];
__device__ float g_gk    [SLOTS*HDIM];
__device__ float g_gv    [SLOTS*HDIM];
__device__ float g_gcnt  [SLOTS];

__device__ bf16 g_wsb[(size_t)MTOK*SLOTS];
__device__ bf16 g_xh [MTOK*HDIM], g_xl [MTOK*HDIM];
__device__ bf16 g_xph[MTOK*HDIM], g_xpl[MTOK*HDIM];
__device__ bf16 g_moh[MTOK*HDIM];
__device__ bf16 g_knh[MTOK*HDIM];
__device__ bf16 g_kmh[SLOTS*HDIM];
__device__ bf16 g_vth[HDIM*SLOTS];
__device__ bf16 g_winh[HDIM*HDIM], g_winl[HDIM*HDIM];
__device__ bf16 g_wqh [HDIM*HDIM], g_wql [HDIM*HDIM];
__device__ bf16 g_wch [1024*512],  g_wcl [1024*512];   // concat(W_kv^T, W_o^T)

// ======================= low-level helpers ======================================
__device__ __forceinline__ uint32_t smem_u32(const void* p) {
    uint32_t a;
    asm("{ .reg .u64 t; cvta.to.shared.u64 t, %1; cvt.u32.u64 %0, t; }" : "=r"(a) : "l"(p));
    return a;
}
__device__ __forceinline__ void cp16(uint32_t s, const void* g) {
    asm volatile("cp.async.cg.shared.global [%0], [%1], 16;" :: "r"(s), "l"(g));
}
#define CP_COMMIT() asm volatile("cp.async.commit_group;" ::: "memory")
#define CP_WAIT(n)  asm volatile("cp.async.wait_group %0;" :: "n"(n) : "memory")

#define LDM4(R, A) asm volatile( \
    "ldmatrix.sync.aligned.m8n8.x4.shared.b16 {%0,%1,%2,%3}, [%4];" \
    : "=r"((R)[0]), "=r"((R)[1]), "=r"((R)[2]), "=r"((R)[3]) : "r"(A))

__device__ __forceinline__ void mma16816(float* c, const uint32_t* a, const uint32_t* b) {
    asm volatile(
        "mma.sync.aligned.m16n8k16.row.col.f32.bf16.bf16.f32 "
        "{%0,%1,%2,%3}, {%4,%5,%6,%7}, {%8,%9}, {%0,%1,%2,%3};"
        : "+f"(c[0]), "+f"(c[1]), "+f"(c[2]), "+f"(c[3])
        : "r"(a[0]), "r"(a[1]), "r"(a[2]), "r"(a[3]), "r"(b[0]), "r"(b[1]));
}
__device__ __forceinline__ uint32_t packbf(float a, float b) {
    __nv_bfloat162 t;
    t.x = __float2bfloat16(a); t.y = __float2bfloat16(b);
    return *(uint32_t*)&t;
}

// ======================= fused conversions + zeroing =============================
#define CB1 8192u
#define CB2 9216u
#define CB3 10240u
#define CB4 10304u
#define CB5 10368u
#define CB6 10752u
#define CB7 10880u
#define CB8 10881u
#define CB9 12929u
#define CBT 12933u

__global__ __launch_bounds__(256)
void fused_conv(const float* __restrict__ x,   const float* __restrict__ Km,
                const float* __restrict__ Vm,  const float* __restrict__ W_in,
                const float* __restrict__ W_q, const float* __restrict__ W_kv,
                const float* __restrict__ W_o, const float* __restrict__ b_kv,
                const float* __restrict__ b_o)
{
    const uint32_t b = blockIdx.x;
    const int tid = threadIdx.x;
    if (b < CB1) {
        long i0 = (long)b * 1024 + tid;
#pragma unroll
        for (int k = 0; k < 4; k++) {
            long i = i0 + k * 256;
            float v = x[i];
            bf16 h = __float2bfloat16(v);
            g_xh[i] = h;
            g_xl[i] = __float2bfloat16(v - __bfloat162float(h));
        }
    } else if (b < CB2) {
        long i0 = (long)(b - CB1) * 1024 + tid;
#pragma unroll
        for (int k = 0; k < 4; k++) {
            long i = i0 + k * 256;
            g_kmh[i] = __float2bfloat16(Km[i]);
        }
    } else if (b < CB3) {
        long i0 = (long)(b - CB2) * 1024 + tid;
#pragma unroll
        for (int k = 0; k < 4; k++) {
            long i = i0 + k * 256;
            int r = (int)(i >> 8), c = (int)(i & 255);
            g_vth[(long)c * SLOTS + r] = __float2bfloat16(Vm[i]);
        }
    } else if (b < CB4) {
        long i0 = (long)(b - CB3) * 1024 + tid;
#pragma unroll
        for (int k = 0; k < 4; k++) {
            long i = i0 + k * 256;
            int r = (int)(i >> 8), c = (int)(i & 255);
            float v = W_in[i];
            bf16 h = __float2bfloat16(v);
            long o = (long)c * 256 + r;
            g_winh[o] = h;
            g_winl[o] = __float2bfloat16(v - __bfloat162float(h));
        }
    } else if (b < CB5) {
        long i0 = (long)(b - CB4) * 1024 + tid;
#pragma unroll
        for (int k = 0; k < 4; k++) {
            long i = i0 + k * 256;
            int r = (int)(i >> 8), c = (int)(i & 255);
            float v = W_q[i];
            bf16 h = __float2bfloat16(v);
            long o = (long)c * 256 + r;
            g_wqh[o] = h;
            g_wql[o] = __float2bfloat16(v - __bfloat162float(h));
        }
    } else if (b < CB6) {
        long i0 = (long)(b - CB5) * 1024 + tid;
#pragma unroll
        for (int k = 0; k < 4; k++) {
            long i = i0 + k * 256;
            int r = (int)(i / 768), c = (int)(i - (long)r * 768);
            float v = W_kv[i];
            bf16 h = __float2bfloat16(v);
            long o = (long)c * 512 + r;
            g_wch[o] = h;
            g_wcl[o] = __float2bfloat16(v - __bfloat162float(h));
        }
    } else if (b < CB7) {
        long i0 = (long)(b - CB6) * 1024 + tid;
#pragma unroll
        for (int k = 0; k < 4; k++) {
            long i = i0 + k * 256;
            int r = (int)(i >> 8), c = (int)(i & 255);
            float v = W_o[i];
            bf16 h = __float2bfloat16(v);
            long o = (long)(768 + c) * 512 + r;
            g_wch[o] = h;
            g_wcl[o] = __float2bfloat16(v - __bfloat162float(h));
        }
    } else if (b < CB8) {
#pragma unroll
        for (int k = 0; k < 4; k++) {
            int i = tid + k * 256;
            g_bcat[i] = (i < 768) ? b_kv[i] : b_o[i - 768];
        }
    } else if (b < CB9) {
        long i0 = (long)(b - CB8) * 1024 + tid;
#pragma unroll
        for (int k = 0; k < 4; k++) {
            long i = i0 + k * 256;
            if (i < (long)SLOTS * HDIM) g_gk[i] = 0.f;
            else g_gv[i - (long)SLOTS * HDIM] = 0.f;
        }
    } else {
        long i0 = (long)(b - CB9) * 1024 + tid;
#pragma unroll
        for (int k = 0; k < 4; k++) {
            long i = i0 + k * 256;
            if (i < SLOTS) g_gcnt[i] = 0.f;
        }
    }
}

// ======================= split-bf16 HMMA GEMM ====================================
#define STG   40960
#define GSMEM (3 * STG)
#define LDSB  80

template<int NS, bool LOA1>
__global__ __launch_bounds__(256, 1)
void gemm_bf16s(const bf16* __restrict__ Ah0, const bf16* __restrict__ Al0, int lda0,
                const bf16* __restrict__ Ah1, const bf16* __restrict__ Al1, int lda1,
                int K0, int K,
                const bf16* __restrict__ Bh, const bf16* __restrict__ Bl,
                const float* __restrict__ bias, float scale,
                float* __restrict__ C, int N,
                bf16* __restrict__ HiO, bf16* __restrict__ LoO,
                bf16* __restrict__ Cb)
{
    extern __shared__ __align__(128) char smx[];
    const uint32_t sb = smem_u32(smx);
    const int tid  = threadIdx.x;
    const int lane = tid & 31, wid = tid >> 5;
    const int wm   = wid & 3,  wn  = wid >> 2;
    const long blkm = (long)blockIdx.y * 128;
    const long blkn = (long)blockIdx.x * 128;
    const int NIT = K >> 5;

    const int r0 = tid >> 2,            c0 = (tid & 3);
    const int r1 = (tid + 256) >> 2,    c1 = ((tid + 256) & 3);

    float acc[2][8][4];
#pragma unroll
    for (int a = 0; a < 2; a++)
#pragma unroll
        for (int b = 0; b < 8; b++)
#pragma unroll
            for (int d = 0; d < 4; d++) acc[a][b][d] = 0.f;

#define LOAD_STAGE(IT) do {                                                        \
        const int _it = (IT);                                                      \
        const int _k0 = _it << 5;                                                  \
        const bf16 *_ah, *_al; long _lda; long _kc;                                \
        if (_k0 < K0) { _ah = Ah0; _al = Al0; _lda = lda0; _kc = _k0; }            \
        else          { _ah = Ah1; _al = Al1; _lda = lda1; _kc = _k0 - K0; }       \
        const bf16* _ar = _ah + blkm * _lda + _kc;                                 \
        const bf16* _br = Bh + blkn * (long)K + _k0;                               \
        const uint32_t _bs = sb + (uint32_t)(_it % 3) * STG;                       \
        cp16(_bs +         (uint32_t)(r0*LDSB + c0*16), _ar  + (long)r0*_lda + c0*8); \
        cp16(_bs +         (uint32_t)(r1*LDSB + c1*16), _ar  + (long)r1*_lda + c1*8); \
        if (NS == 3 && (LOA1 || _k0 < K0)) {                                       \
            const bf16* _alr = _al + blkm * _lda + _kc;                            \
            cp16(_bs + 10240 + (uint32_t)(r0*LDSB + c0*16), _alr + (long)r0*_lda + c0*8); \
            cp16(_bs + 10240 + (uint32_t)(r1*LDSB + c1*16), _alr + (long)r1*_lda + c1*8); \
        }                                                                          \
        cp16(_bs + 20480 + (uint32_t)(r0*LDSB + c0*16), _br  + (long)r0*K + c0*8);    \
        cp16(_bs + 20480 + (uint32_t)(r1*LDSB + c1*16), _br  + (long)r1*K + c1*8);    \
        if (NS >= 2) {                                                             \
            const bf16* _blr = Bl + blkn * (long)K + _k0;                          \
            cp16(_bs + 30720 + (uint32_t)(r0*LDSB + c0*16), _blr + (long)r0*K + c0*8);    \
            cp16(_bs + 30720 + (uint32_t)(r1*LDSB + c1*16), _blr + (long)r1*K + c1*8);    \
        }                                                                          \
        CP_COMMIT();                                                               \
    } while (0)

    LOAD_STAGE(0);
    if (NIT > 1) LOAD_STAGE(1);

    const uint32_t a_off = (uint32_t)((wm*32 + (lane & 15)) * LDSB + (lane >> 4) * 16);
    const uint32_t b_off = (uint32_t)((wn*64 + ((lane >> 4) << 3) + (lane & 7)) * LDSB
                                      + ((lane >> 3) & 1) * 16);

    for (int it = 0; it < NIT; it++) {
        if (it + 1 < NIT) CP_WAIT(1); else CP_WAIT(0);
        __syncthreads();
        const bool doAL = (NS == 3) && (LOA1 || (it << 5) < K0);
        const uint32_t base = sb + (uint32_t)(it % 3) * STG;
#pragma unroll
        for (int kk = 0; kk < 2; kk++) {
            const uint32_t ka = base + a_off + kk * 32;
            const uint32_t kb = base + b_off + kk * 32;
            uint32_t AH[2][4], AL[2][4], BH[4][4], BL[4][4];
            LDM4(AH[0], ka);
            LDM4(AH[1], ka + 16 * LDSB);
            if (NS == 3 && doAL) {
                LDM4(AL[0], ka + 10240);
                LDM4(AL[1], ka + 10240 + 16 * LDSB);
            }
#pragma unroll
            for (int p = 0; p < 4; p++) {
                LDM4(BH[p], kb + 20480 + p * 16 * LDSB);
                if (NS >= 2) LDM4(BL[p], kb + 30720 + p * 16 * LDSB);
            }
#pragma unroll
            for (int mf = 0; mf < 2; mf++)
#pragma unroll
                for (int nf = 0; nf < 8; nf++) {
                    const uint32_t* bh = &BH[nf >> 1][(nf & 1) * 2];
                    mma16816(acc[mf][nf], AH[mf], bh);
                    if (NS >= 2) {
                        const uint32_t* bl = &BL[nf >> 1][(nf & 1) * 2];
                        mma16816(acc[mf][nf], AH[mf], bl);
                    }
                    if (NS == 3 && doAL) mma16816(acc[mf][nf], AL[mf], bh);
                }
        }
        if (it + 2 < NIT) LOAD_STAGE(it + 2);
    }

#pragma unroll
    for (int mf = 0; mf < 2; mf++) {
        const long m0 = blkm + wm * 32 + mf * 16 + (lane >> 2);
#pragma unroll
        for (int nf = 0; nf < 8; nf++) {
            const long n0 = blkn + wn * 64 + nf * 8 + (lane & 3) * 2;
            float b0 = bias ? bias[n0]     : 0.f;
            float b1 = bias ? bias[n0 + 1] : 0.f;
            float2 v0, v1;
            v0.x = acc[mf][nf][0] * scale + b0;
            v0.y = acc[mf][nf][1] * scale + b1;
            v1.x = acc[mf][nf][2] * scale + b0;
            v1.y = acc[mf][nf][3] * scale + b1;
            if (Cb) {
                *(uint32_t*)(Cb + m0 * (long)N + n0)       = packbf(v0.x, v0.y);
                *(uint32_t*)(Cb + (m0 + 8) * (long)N + n0) = packbf(v1.x, v1.y);
            } else {
                *(float2*)(C + m0 * (long)N + n0)       = v0;
                *(float2*)(C + (m0 + 8) * (long)N + n0) = v1;
                if (HiO) {
                    __nv_bfloat162 h0, h1, l0, l1;
                    h0.x = __float2bfloat16(v0.x); h0.y = __float2bfloat16(v0.y);
                    h1.x = __float2bfloat16(v1.x); h1.y = __float2bfloat16(v1.y);
                    l0.x = __float2bfloat16(v0.x - __bfloat162float(h0.x));
                    l0.y = __float2bfloat16(v0.y - __bfloat162float(h0.y));
                    l1.x = __float2bfloat16(v1.x - __bfloat162float(h1.x));
                    l1.y = __float2bfloat16(v1.y - __bfloat162float(h1.y));
                    *(__nv_bfloat162*)(HiO + m0 * (long)N + n0)       = h0;
                    *(__nv_bfloat162*)(HiO + (m0 + 8) * (long)N + n0) = h1;
                    *(__nv_bfloat162*)(LoO + m0 * (long)N + n0)       = l0;
                    *(__nv_bfloat162*)(LoO + (m0 + 8) * (long)N + n0) = l1;
                }
            }
        }
    }
#undef LOAD_STAGE
}

// ======================= fused flash attention (R14 tiling, 1 sync/iter) ========
#define LDQ 528
#define LDK 528
#define LDV 144
#define OQ  0
#define OK0 67584
#define OK1 101376
#define OV0 135168
#define OV1 172032
#define FA_SMEM 208896

#define LOADK(S0, BUF) do {                                                 \
        const bf16* _kh = Kh + (long)(S0) * HDIM;                           \
        const uint32_t _b = sb + ((BUF) ? OK1 : OK0);                       \
        _Pragma("unroll")                                                   \
        for (int _i = 0; _i < 8; _i++) {                                    \
            int _idx = tid + (_i << 8);                                     \
            int _r = _idx >> 5, _c = _idx & 31;                             \
            cp16(_b + (uint32_t)(_r * LDK + _c * 16), _kh + (long)_r * HDIM + _c * 8); \
        }                                                                   \
        CP_COMMIT();                                                        \
    } while (0)

#define LOADV(S0, BUF) do {                                                 \
        const uint32_t _b = sb + ((BUF) ? OV1 : OV0);                       \
        _Pragma("unroll")                                                   \
        for (int _i = 0; _i < 8; _i++) {                                    \
            int _idx = tid + (_i << 8);                                     \
            int _r = _idx >> 3, _c = _idx & 7;                              \
            cp16(_b + (uint32_t)(_r * LDV + _c * 16), Vth + (long)_r * SLOTS + (S0) + _c * 8); \
        }                                                                   \
        CP_COMMIT();                                                        \
    } while (0)

__global__ __launch_bounds__(256, 1)
void attn_fused(const float* __restrict__ Qpre, const float* __restrict__ gq,
                const float* __restrict__ beq,
                const bf16* __restrict__ Kh, const bf16* __restrict__ Vth,
                bf16* __restrict__ MOh, float* __restrict__ surp)
{
    extern __shared__ __align__(128) char smx[];
    const uint32_t sb = smem_u32(smx);
    const int tid = threadIdx.x, lane = tid & 31, wid = tid >> 5;
    const long row0 = (long)blockIdx.x * 128;

    LOADK(0, 0);
    LOADV(0, 0);

    // --- fused LN + exact GELU prologue (overlaps K/V cp.async) ---
    {
        float gv[8], bv[8];
        *(float4*)&gv[0] = *(const float4*)(gq  + lane * 8);
        *(float4*)&gv[4] = *(const float4*)(gq  + lane * 8 + 4);
        *(float4*)&bv[0] = *(const float4*)(beq + lane * 8);
        *(float4*)&bv[4] = *(const float4*)(beq + lane * 8 + 4);
#pragma unroll 2
        for (int rr = 0; rr < 16; rr++) {
            const int rl = wid * 16 + rr;
            const float* qr = Qpre + (row0 + rl) * HDIM + lane * 8;
            float v[8];
            *(float4*)&v[0] = *(const float4*)qr;
            *(float4*)&v[4] = *(const float4*)(qr + 4);
            float s = 0.f;
#pragma unroll
            for (int j = 0; j < 8; j++) s += v[j];
#pragma unroll
            for (int o = 16; o > 0; o >>= 1) s += __shfl_xor_sync(0xffffffffu, s, o);
            const float mean = s * (1.f / 256.f);
            float sq = 0.f;
#pragma unroll
            for (int j = 0; j < 8; j++) { float d = v[j] - mean; sq += d * d; }
#pragma unroll
            for (int o = 16; o > 0; o >>= 1) sq += __shfl_xor_sync(0xffffffffu, sq, o);
            const float rstd = rsqrtf(sq * (1.f / 256.f) + 1e-5f);
            uint32_t pk[4];
#pragma unroll
            for (int j = 0; j < 4; j++) {
                float t0 = (v[2*j]   - mean) * rstd * gv[2*j]   + bv[2*j];
                float t1 = (v[2*j+1] - mean) * rstd * gv[2*j+1] + bv[2*j+1];
                float g0 = 0.5f * t0 * (1.f + erff(t0 * 0.70710678f));
                float g1 = 0.5f * t1 * (1.f + erff(t1 * 0.70710678f));
                pk[j] = packbf(g0, g1);
            }
            uint32_t dst = sb + OQ + (uint32_t)(rl * LDQ + lane * 16);
            asm volatile("st.shared.v4.b32 [%0], {%1,%2,%3,%4};"
                         :: "r"(dst), "r"(pk[0]), "r"(pk[1]), "r"(pk[2]), "r"(pk[3]));
        }
    }

    const uint32_t a_off  = sb + OQ + (uint32_t)((wid * 16 + (lane & 15)) * LDQ + (lane >> 4) * 16);
    const uint32_t bk_off = (uint32_t)(((((lane >> 4) << 3) + (lane & 7)) * LDK) + ((lane >> 3) & 1) * 16);
    const uint32_t bv_off = (uint32_t)(((((lane >> 4) << 3) + (lane & 7)) * LDV) + ((lane >> 3) & 1) * 16);

    float oacc[32][4];
#pragma unroll
    for (int i = 0; i < 32; i++)
#pragma unroll
        for (int j = 0; j < 4; j++) oacc[i][j] = 0.f;
    float m0 = -INFINITY, m1 = -INFINITY, l0 = 0.f, l1 = 0.f;

    for (int s = 0; s < 64; s++) {
        const uint32_t kb_base = sb + ((s & 1) ? OK1 : OK0);
        const uint32_t vb_base = sb + ((s & 1) ? OV1 : OV0);

        CP_WAIT(0);                  // K(s) and V(s) resident
        __syncthreads();             // everyone done reading buffer (s+1)&1 from iter s-1
        if (s + 1 < 64) {            // prefetch both tiles into the now-free buffer
            LOADK((s + 1) * 64, (s + 1) & 1);
            LOADV((s + 1) * 64, (s + 1) & 1);
        }

        float sacc[8][4];
#pragma unroll
        for (int nf = 0; nf < 8; nf++)
#pragma unroll
            for (int j = 0; j < 4; j++) sacc[nf][j] = 0.f;

#pragma unroll 4
        for (int kk = 0; kk < 16; kk++) {
            uint32_t A[4], BH[4][4];
            LDM4(A, a_off + kk * 32);
#pragma unroll
            for (int p = 0; p < 4; p++)
                LDM4(BH[p], kb_base + bk_off + (uint32_t)(p * 16 * LDK) + kk * 32);
#pragma unroll
            for (int nf = 0; nf < 8; nf++)
                mma16816(sacc[nf], A, &BH[nf >> 1][(nf & 1) * 2]);
        }

        float tm0 = -INFINITY, tm1 = -INFINITY;
#pragma unroll
        for (int nf = 0; nf < 8; nf++) {
            tm0 = fmaxf(tm0, fmaxf(sacc[nf][0], sacc[nf][1]));
            tm1 = fmaxf(tm1, fmaxf(sacc[nf][2], sacc[nf][3]));
        }
        tm0 = fmaxf(tm0, __shfl_xor_sync(0xffffffffu, tm0, 1));
        tm0 = fmaxf(tm0, __shfl_xor_sync(0xffffffffu, tm0, 2));
        tm1 = fmaxf(tm1, __shfl_xor_sync(0xffffffffu, tm1, 1));
        tm1 = fmaxf(tm1, __shfl_xor_sync(0xffffffffu, tm1, 2));
        tm0 *= 0.0625f; tm1 *= 0.0625f;
        const float nm0 = fmaxf(m0, tm0), nm1 = fmaxf(m1, tm1);
        const float al0 = __expf(m0 - nm0),  al1 = __expf(m1 - nm1);

        uint32_t PH[4][4];
        float ls0 = 0.f, ls1 = 0.f;
#pragma unroll
        for (int nf = 0; nf < 8; nf++) {
            float p0 = __expf(fmaf(sacc[nf][0], 0.0625f, -nm0));
            float p1 = __expf(fmaf(sacc[nf][1], 0.0625f, -nm0));
            float p2 = __expf(fmaf(sacc[nf][2], 0.0625f, -nm1));
            float p3 = __expf(fmaf(sacc[nf][3], 0.0625f, -nm1));
            ls0 += p0 + p1; ls1 += p2 + p3;
            const int kc = nf >> 1, bi = (nf & 1) * 2;
            PH[kc][bi]     = packbf(p0, p1);
            PH[kc][bi + 1] = packbf(p2, p3);
        }
        ls0 += __shfl_xor_sync(0xffffffffu, ls0, 1);
        ls0 += __shfl_xor_sync(0xffffffffu, ls0, 2);
        ls1 += __shfl_xor_sync(0xffffffffu, ls1, 1);
        ls1 += __shfl_xor_sync(0xffffffffu, ls1, 2);
        l0 = l0 * al0 + ls0;
        l1 = l1 * al1 + ls1;
        m0 = nm0; m1 = nm1;
#pragma unroll
        for (int i = 0; i < 32; i++) {
            oacc[i][0] *= al0; oacc[i][1] *= al0;
            oacc[i][2] *= al1; oacc[i][3] *= al1;
        }

#pragma unroll
        for (int kc = 0; kc < 4; kc++) {
#pragma unroll
            for (int g = 0; g < 16; g++) {
                uint32_t VH[4];
                LDM4(VH, vb_base + bv_off + (uint32_t)(g * 16 * LDV) + kc * 32);
                mma16816(oacc[2*g],     PH[kc], &VH[0]);
                mma16816(oacc[2*g + 1], PH[kc], &VH[2]);
            }
        }
    }

    const float inv0 = 1.f / l0, inv1 = 1.f / l1;
    const long gr0 = row0 + wid * 16 + (lane >> 2);
    const long gr1 = gr0 + 8;
#pragma unroll
    for (int nf2 = 0; nf2 < 32; nf2++) {
        const int c = nf2 * 8 + (lane & 3) * 2;
        *(uint32_t*)(MOh + gr0 * HDIM + c) = packbf(oacc[nf2][0] * inv0, oacc[nf2][1] * inv0);
        *(uint32_t*)(MOh + gr1 * HDIM + c) = packbf(oacc[nf2][2] * inv1, oacc[nf2][3] * inv1);
    }
    if ((lane & 3) == 0) {
        surp[gr0] = 1.f - inv0;
        surp[gr1] = 1.f - inv1;
    }
}

// ======================= reductions ==============================================
__device__ __forceinline__ float block_sum_256(float v, float* red)
{
#pragma unroll
    for (int o = 16; o > 0; o >>= 1) v += __shfl_xor_sync(0xffffffffu, v, o);
    if ((threadIdx.x & 31) == 0) red[threadIdx.x >> 5] = v;
    __syncthreads();
    float t = 0.f;
#pragma unroll
    for (int i = 0; i < 8; i++) t += red[i];
    __syncthreads();
    return t;
}
__device__ __forceinline__ float block_max_256(float v, float* red)
{
#pragma unroll
    for (int o = 16; o > 0; o >>= 1) v = fmaxf(v, __shfl_xor_sync(0xffffffffu, v, o));
    if ((threadIdx.x & 31) == 0) red[threadIdx.x >> 5] = v;
    __syncthreads();
    float t = -INFINITY;
#pragma unroll
    for (int i = 0; i < 8; i++) t = fmaxf(t, red[i]);
    __syncthreads();
    return t;
}

// ======================= merged kv LN+GELU + final double-LN =====================
__global__ __launch_bounds__(256)
void ln_kv_final(float* __restrict__ kvo, const float* __restrict__ gkv,
                 const float* __restrict__ bekv, bf16* __restrict__ knh,
                 float* __restrict__ lr,
                 const float* __restrict__ xproj,
                 const float* __restrict__ go, const float* __restrict__ beo,
                 const float* __restrict__ g1, const float* __restrict__ be1,
                 float* __restrict__ out)
{
    __shared__ float red[8];
    const long row = blockIdx.x; const int tid = threadIdx.x;
    float* xr = kvo + row * 1024;

    float vals[3];
    float s = 0.f;
#pragma unroll
    for (int i = 0; i < 3; i++) { vals[i] = xr[tid + (i << 8)]; s += vals[i]; }
    float mean = block_sum_256(s, red) * (1.f / 768.f);
    float sq = 0.f;
#pragma unroll
    for (int i = 0; i < 3; i++) { float d = vals[i] - mean; sq += d * d; }
    float var  = block_sum_256(sq, red) * (1.f / 768.f);
    float rstd = rsqrtf(var + 1e-5f);
    float gout[3];
#pragma unroll
    for (int i = 0; i < 3; i++) {
        int c = tid + (i << 8);
        float t = (vals[i] - mean) * rstd * gkv[c] + bekv[c];
        gout[i] = 0.5f * t * (1.f + erff(t * 0.70710678f));
    }
    xr[tid]       = gout[0];
    xr[tid + 256] = gout[1];
    knh[row * HDIM + tid] = __float2bfloat16(gout[0]);
    float sg = 1.f / (1.f + __expf(-gout[2]));
    float tot = block_sum_256(sg, red);
    if (tid == 0) lr[row] = tot * (1.f / 256.f);

    float v    = xr[768 + tid];
    float m1   = block_sum_256(v, red) * (1.f / 256.f);
    float d    = v - m1;
    float var2 = block_sum_256(d * d, red) * (1.f / 256.f);
    float t    = d * rsqrtf(var2 + 1e-5f) * go[tid] + beo[tid];
    float u    = t + xproj[row * HDIM + tid];
    float m2   = block_sum_256(u, red) * (1.f / 256.f);
    float d2   = u - m2;
    float v2   = block_sum_256(d2 * d2, red) * (1.f / 256.f);
    out[row * HDIM + tid] = d2 * rsqrtf(v2 + 1e-5f) * g1[tid] + be1[tid];
}

__global__ void memupd_kernel(const float* __restrict__ Km, const float* __restrict__ Vm,
                              float* __restrict__ Kout, float* __restrict__ Vout)
{
    int i = blockIdx.x * blockDim.x + threadIdx.x;
    float cnt = g_gcnt[i >> 8];
    float k = Km[i], v = Vm[i];
    Kout[i] = k + 0.1f * (g_gk[i] - cnt * k);
    Vout[i] = v + 0.1f * (g_gv[i] - cnt * v);
}

// ======================= exact argmax + gated scatter ===========================
__global__ __launch_bounds__(256)
void argmax_scatter(const bf16* __restrict__ wsim, const float* __restrict__ kvo,
                    const float* __restrict__ Km, const float* __restrict__ surp)
{
    __shared__ float red[8];
    __shared__ int s_cnt;
    __shared__ int s_cand[128];
    const long row = blockIdx.x;
    const int tid = threadIdx.x;
    const bf16* wr = wsim + row * SLOTS;
    float v[16], mloc = -INFINITY;
#pragma unroll
    for (int i = 0; i < 16; i++) {
        v[i] = __bfloat162float(wr[tid + (i << 8)]);
        mloc = fmaxf(mloc, v[i]);
    }
    float m = block_max_256(mloc, red);
    if (tid == 0) s_cnt = 0;
    __syncthreads();
#pragma unroll
    for (int i = 0; i < 16; i++) {
        if (v[i] >= m - 1e-1f) {
            int p = atomicAdd(&s_cnt, 1);
            if (p < 128) s_cand[p] = tid + (i << 8);
        }
    }
    __syncthreads();
    int n = s_cnt < 128 ? s_cnt : 128;
    const float kn = kvo[row * 1024 + tid];
    float bestv = -INFINITY; int besti = 0x7fffffff;
    for (int j = 0; j < n; j++) {
        int slot = s_cand[j];
        float s = block_sum_256(kn * Km[(long)slot * HDIM + tid], red);
        if (s > bestv || (s == bestv && slot < besti)) { bestv = s; besti = slot; }
    }
    float gate = surp[row];
    atomicAdd(&g_gk[(long)besti * HDIM + tid], gate * kn);
    atomicAdd(&g_gv[(long)besti * HDIM + tid], gate * kvo[row * 1024 + 256 + tid]);
    if (tid == 0) atomicAdd(&g_gcnt[besti], gate);
}

// =================================================================================
extern "C" void kernel_launch(void* const* d_in, const int* in_sizes, int n_in,
                              void* d_out, int out_size)
{
    const float* x    = (const float*)d_in[0];
    const float* W_in = (const float*)d_in[1];
    const float* b_in = (const float*)d_in[2];
    const float* W_q  = (const float*)d_in[3];
    const float* b_q  = (const float*)d_in[4];
    const float* gq   = (const float*)d_in[5];
    const float* beq  = (const float*)d_in[6];
    const float* Km   = (const float*)d_in[7];
    const float* Vm   = (const float*)d_in[8];
    const float* W_kv = (const float*)d_in[9];
    const float* b_kv = (const float*)d_in[10];
    const float* gkv  = (const float*)d_in[11];
    const float* bekv = (const float*)d_in[12];
    const float* W_o  = (const float*)d_in[13];
    const float* b_o  = (const float*)d_in[14];
    const float* go   = (const float*)d_in[15];
    const float* beo  = (const float*)d_in[16];
    const float* g1   = (const float*)d_in[17];
    const float* be1  = (const float*)d_in[18];

    float* out    = (float*)d_out;
    float* o_out  = out;
    float* k_out  = out + 8388608;
    float* v_out  = out + 9437184;
    float* s_out  = out + 10485760;
    float* lr_out = out + 10518528;

    float *p_xproj, *p_query, *p_kvo, *p_bcat;
    cudaGetSymbolAddress((void**)&p_xproj, g_xproj);
    cudaGetSymbolAddress((void**)&p_query, g_query);
    cudaGetSymbolAddress((void**)&p_kvo,   g_kvo);
    cudaGetSymbolAddress((void**)&p_bcat,  g_bcat);
    bf16 *wsb,*xh,*xl,*xph,*xpl,*moh,*knh,*kmh,*vth;
    bf16 *winh,*winl,*wqh,*wql,*wch,*wcl;
    cudaGetSymbolAddress((void**)&wsb, g_wsb);
    cudaGetSymbolAddress((void**)&xh,  g_xh);  cudaGetSymbolAddress((void**)&xl,  g_xl);
    cudaGetSymbolAddress((void**)&xph, g_xph); cudaGetSymbolAddress((void**)&xpl, g_xpl);
    cudaGetSymbolAddress((void**)&moh, g_moh);
    cudaGetSymbolAddress((void**)&knh, g_knh);
    cudaGetSymbolAddress((void**)&kmh, g_kmh);
    cudaGetSymbolAddress((void**)&vth, g_vth);
    cudaGetSymbolAddress((void**)&winh,g_winh);cudaGetSymbolAddress((void**)&winl,g_winl);
    cudaGetSymbolAddress((void**)&wqh, g_wqh); cudaGetSymbolAddress((void**)&wql, g_wql);
    cudaGetSymbolAddress((void**)&wch, g_wch); cudaGetSymbolAddress((void**)&wcl, g_wcl);

    cudaFuncSetAttribute((const void*)gemm_bf16s<3,true>,  cudaFuncAttributeMaxDynamicSharedMemorySize, GSMEM);
    cudaFuncSetAttribute((const void*)gemm_bf16s<3,false>, cudaFuncAttributeMaxDynamicSharedMemorySize, GSMEM);
    cudaFuncSetAttribute((const void*)gemm_bf16s<2,true>,  cudaFuncAttributeMaxDynamicSharedMemorySize, GSMEM);
    cudaFuncSetAttribute((const void*)gemm_bf16s<1,true>,  cudaFuncAttributeMaxDynamicSharedMemorySize, GSMEM);
    cudaFuncSetAttribute((const void*)attn_fused,          cudaFuncAttributeMaxDynamicSharedMemorySize, FA_SMEM);

    fused_conv<<<CBT, 256>>>(x, Km, Vm, W_in, W_q, W_kv, W_o, b_kv, b_o);

    // x_proj = x @ W_in + b_in  (NS=3; fused hi/lo out)
    gemm_bf16s<3,true><<<dim3(2,256), 256, GSMEM>>>(xh, xl, 256, xh, xl, 256, 256, 256,
                                                    winh, winl, b_in, 1.f, p_xproj, 256, xph, xpl, nullptr);

    // q_pre = x_proj @ W_q + b_q  (NS=2); LN+GELU fused into attn prologue
    gemm_bf16s<2,true><<<dim3(2,256), 256, GSMEM>>>(xph, nullptr, 256, xph, nullptr, 256, 256, 256,
                                                    wqh, wql, b_q, 1.f, p_query, 256, nullptr, nullptr, nullptr);

    // fused: LN+GELU(q) -> sim (NS=1) -> softmax -> mem_out (PV NS=1) + surprise
    attn_fused<<<256, 256, FA_SMEM>>>(p_query, gq, beq, kmh, vth, moh, s_out);

    // merged [kv_lr | opre] GEMM (NS=3, mo half lo-free)
    gemm_bf16s<3,false><<<dim3(8,256), 256, GSMEM>>>(xph, xpl, 256, moh, nullptr, 256, 256, 512,
                                                     wch, wcl, p_bcat, 1.f, p_kvo, 1024, nullptr, nullptr, nullptr);

    // merged: LN+GELU(kv) + lr + final double-LN -> out
    ln_kv_final<<<32768, 256>>>(p_kvo, gkv, bekv, knh, lr_out,
                                p_xproj, go, beo, g1, be1, o_out);

    // wsim = key_new @ K_mem^T  (NS=1, bf16 out), then exact argmax + scatter
    gemm_bf16s<1,true><<<dim3(32,256), 256, GSMEM>>>(knh, nullptr, 256, knh, nullptr, 256, 256, 256,
                                                     kmh, nullptr, nullptr, 1.f, nullptr, SLOTS, nullptr, nullptr, wsb);
    argmax_scatter<<<32768, 256>>>(wsb, p_kvo, Km, s_out);
    memupd_kernel<<<4096, 256>>>(Km, Vm, k_out, v_out);
}